// round 15
// baseline (speedup 1.0000x reference)
#include <cuda_runtime.h>
#include <cuda_bf16.h>
#include <cstdint>
#include <cstddef>

#define T_STEPS 512
#define BATCH   64
#define EMBD    512
#define RNNSZ   1024
#define G3      3072
#define NCTA    64
#define UPC     16          // hidden units per recurrence CTA
#define NCOL    48          // 3 gates * 16 units

// ------------------------- device scratch (no allocation) -------------------------
__device__ float g_gi[(size_t)T_STEPS * BATCH * G3];   // gi_all = emb[x] @ w_ih^T + b_ih
__device__ float g_h32[2][BATCH * RNNSZ];              // fp32 hidden state (ping-pong)
__device__ float g_hr [2][BATCH * RNNSZ];              // tf32-rounded hidden, k-permuted layout
__device__ volatile int g_flags[NCTA];                 // grid barrier flags

// ------------------------- helpers -------------------------
__device__ __forceinline__ float f2tf_f(float f) {
    unsigned u;
    asm("cvt.rna.tf32.f32 %0, %1;" : "=r"(u) : "f"(f));
    return __uint_as_float(u);
}

__device__ __forceinline__ void mma8(float c[4],
                                     unsigned a0, unsigned a1, unsigned a2, unsigned a3,
                                     unsigned b0, unsigned b1) {
    asm volatile(
        "mma.sync.aligned.m16n8k8.row.col.f32.tf32.tf32.f32 "
        "{%0,%1,%2,%3},{%4,%5,%6,%7},{%8,%9},{%0,%1,%2,%3};"
        : "+f"(c[0]), "+f"(c[1]), "+f"(c[2]), "+f"(c[3])
        : "r"(a0), "r"(a1), "r"(a2), "r"(a3), "r"(b0), "r"(b1));
}

// ------------------------- init -------------------------
__global__ void init_kernel() {
    int i = blockIdx.x * blockDim.x + threadIdx.x;
    if (i < BATCH * RNNSZ) { g_h32[0][i] = 0.f; g_hr[0][i] = 0.f; }
    if (blockIdx.x == 0 && threadIdx.x < NCTA) g_flags[threadIdx.x] = 0;
}

// ------------------------- phase 1: gi GEMM (gather fused) -------------------------
// C tile 128x128, K-chunk 32, 256 threads: 8 warps = 4(M) x 2(N),
// warp tile 32x64 = 2 m-tiles x 8 n-tiles of m16n8k8 tf32.
__global__ __launch_bounds__(256) void gi_kernel(const int* __restrict__ x,
                                                 const float* __restrict__ emb,
                                                 const float* __restrict__ w_ih,
                                                 const float* __restrict__ b_ih) {
    __shared__ float As[128][36];
    __shared__ float Bs[128][36];
    __shared__ int   toks[128];

    const int tid = threadIdx.x;
    const int m0 = blockIdx.y * 128;
    const int n0 = blockIdx.x * 128;
    if (tid < 128) toks[tid] = x[m0 + tid];
    __syncthreads();

    const int w = tid >> 5, lane = tid & 31;
    const int wm = (w & 3) * 32;
    const int wn = (w >> 2) * 64;

    float acc[2][8][4];
#pragma unroll
    for (int a = 0; a < 2; a++)
#pragma unroll
        for (int b = 0; b < 8; b++)
#pragma unroll
            for (int q = 0; q < 4; q++) acc[a][b][q] = 0.f;

    const int lrow = tid >> 1;
    const int lcb  = (tid & 1) * 16;
    const float* aptr = emb  + (size_t)toks[lrow] * EMBD + lcb;
    const float* bptr = w_ih + (size_t)(n0 + lrow) * EMBD + lcb;

    for (int kc = 0; kc < EMBD; kc += 32) {
#pragma unroll
        for (int q = 0; q < 4; q++) {
            float4 va = *(const float4*)(aptr + kc + q * 4);
            *(float4*)&As[lrow][lcb + q * 4] =
                make_float4(f2tf_f(va.x), f2tf_f(va.y), f2tf_f(va.z), f2tf_f(va.w));
            float4 vb = *(const float4*)(bptr + kc + q * 4);
            *(float4*)&Bs[lrow][lcb + q * 4] =
                make_float4(f2tf_f(vb.x), f2tf_f(vb.y), f2tf_f(vb.z), f2tf_f(vb.w));
        }
        __syncthreads();
#pragma unroll
        for (int ks = 0; ks < 4; ks++) {
            const int cc = ks * 8 + (lane & 3);
            unsigned a[2][4];
#pragma unroll
            for (int mt = 0; mt < 2; mt++) {
                int r = wm + mt * 16 + (lane >> 2);
                a[mt][0] = __float_as_uint(As[r][cc]);
                a[mt][1] = __float_as_uint(As[r + 8][cc]);
                a[mt][2] = __float_as_uint(As[r][cc + 4]);
                a[mt][3] = __float_as_uint(As[r + 8][cc + 4]);
            }
#pragma unroll
            for (int nt = 0; nt < 8; nt++) {
                int cl = wn + nt * 8 + (lane >> 2);
                unsigned b0 = __float_as_uint(Bs[cl][cc]);
                unsigned b1 = __float_as_uint(Bs[cl][cc + 4]);
                mma8(acc[0][nt], a[0][0], a[0][1], a[0][2], a[0][3], b0, b1);
                mma8(acc[1][nt], a[1][0], a[1][1], a[1][2], a[1][3], b0, b1);
            }
        }
        __syncthreads();
    }

#pragma unroll
    for (int mt = 0; mt < 2; mt++)
#pragma unroll
        for (int nt = 0; nt < 8; nt++) {
            int row = m0 + wm + mt * 16 + (lane >> 2);
            int col = n0 + wn + nt * 8 + (lane & 3) * 2;
            float2 bias = *(const float2*)(b_ih + col);
            float2 v0 = make_float2(acc[mt][nt][0] + bias.x, acc[mt][nt][1] + bias.y);
            float2 v1 = make_float2(acc[mt][nt][2] + bias.x, acc[mt][nt][3] + bias.y);
            *(float2*)&g_gi[(size_t)row * G3 + col]       = v0;
            *(float2*)&g_gi[(size_t)(row + 8) * G3 + col] = v1;
        }
}

// ------------------------- phase 2: persistent recurrence -------------------------
// 64 CTAs x 256 thr. CTA c owns hidden units [16c, 16c+16) -> 48 gh columns.
// Weights tf32-packed in smem (mma B-fragment order). Warps = 2(M-half) x 4(K-quarter).
// h stored in permuted k-order so A-fragments for 2 k-steps come from one LDG.128.
// Smem: smw 192KB | P0,P1 (64x50 each) | bhh(48).
#define SMW_FLOATS (NCOL * RNNSZ)            // 49152
#define P_STRIDE   50
#define P_FLOATS   (BATCH * P_STRIDE)        // 3200
#define REC_SMEM   ((SMW_FLOATS + 2 * P_FLOATS + 64) * 4)

__global__ __launch_bounds__(256, 1) void rec_kernel(const float* __restrict__ w_hh,
                                                     const float* __restrict__ b_hh) {
    extern __shared__ float sm[];
    float* smw = sm;
    float* P0  = sm + SMW_FLOATS;
    float* P1  = P0 + P_FLOATS;               // also the final Ss buffer
    float* bhh = P1 + P_FLOATS;

    const int c   = blockIdx.x;
    const int tid = threadIdx.x;

    // ---- one-time: pack weights (tf32, B-fragment order) ----
    for (int idx = tid; idx < NCOL * RNNSZ; idx += 256) {
        int i = idx >> 10;                    // col-set 0..47
        int k = idx & (RNNSZ - 1);
        int gate = i >> 4, u = i & 15;
        float v = f2tf_f(w_hh[(size_t)(gate * RNNSZ + c * UPC + u) * RNNSZ + k]);
        int j = i >> 3, n_in = i & 7, ksg = k >> 3, kk = k & 7;
        int ln = n_in * 4 + (kk & 3), slot = kk >> 2;
        smw[((j * 128 + ksg) * 32 + ln) * 2 + slot] = v;
    }
    if (tid < NCOL) {
        int gate = tid >> 4, u = tid & 15;
        bhh[tid] = b_hh[gate * RNNSZ + c * UPC + u];
    }
    __syncthreads();

    const int w = tid >> 5, lane = tid & 31;
    const int wm = w & 1;                     // M half (rows 32*wm .. +32)
    const int wk = w >> 1;                    // K quarter

    for (int t = 0; t < T_STEPS; t++) {
        const float* hr = g_hr[t & 1];
        float acc[2][6][4];
#pragma unroll
        for (int mt = 0; mt < 2; mt++)
#pragma unroll
            for (int j = 0; j < 6; j++)
#pragma unroll
                for (int q = 0; q < 4; q++) acc[mt][j][q] = 0.f;

        // ---- gh mma over this warp's K quarter (16 groups of 16 k) ----
        const int gbase = wk * 16;
#pragma unroll 2
        for (int g16 = 0; g16 < 16; g16++) {
            const int gg = gbase + g16;
            unsigned av[2][8];                // [mt][ 2 k-steps x {a0,a1,a2,a3} ]
#pragma unroll
            for (int mt = 0; mt < 2; mt++) {
                int rb = 32 * wm + 16 * mt + (lane >> 2);
                const float4 va = *(const float4*)(hr + (size_t)rb * RNNSZ + gg * 16 + 4 * (lane & 3));
                const float4 vb = *(const float4*)(hr + (size_t)(rb + 8) * RNNSZ + gg * 16 + 4 * (lane & 3));
                av[mt][0] = __float_as_uint(va.x); av[mt][1] = __float_as_uint(vb.x);
                av[mt][2] = __float_as_uint(va.y); av[mt][3] = __float_as_uint(vb.y);
                av[mt][4] = __float_as_uint(va.z); av[mt][5] = __float_as_uint(vb.z);
                av[mt][6] = __float_as_uint(va.w); av[mt][7] = __float_as_uint(vb.w);
            }
#pragma unroll
            for (int ksl = 0; ksl < 2; ksl++) {
                const int ksg = gg * 2 + ksl;
#pragma unroll
                for (int j = 0; j < 6; j++) {
                    const float2 bb = *(const float2*)&smw[((j * 128 + ksg) * 32 + lane) * 2];
                    unsigned b0 = __float_as_uint(bb.x), b1 = __float_as_uint(bb.y);
                    mma8(acc[0][j], av[0][ksl*4+0], av[0][ksl*4+1], av[0][ksl*4+2], av[0][ksl*4+3], b0, b1);
                    mma8(acc[1][j], av[1][ksl*4+0], av[1][ksl*4+1], av[1][ksl*4+2], av[1][ksl*4+3], b0, b1);
                }
            }
        }

        // ---- reduce 4 K-quarters: wk3->P0, wk1->P1; wk2+=P0, wk0+=P1; wk2->P0; wk0+=P0 ----
        const int colb = 2 * (lane & 3);
#pragma unroll 1
        for (int phase = 0; phase < 1; phase++) {
            if (wk == 3 || wk == 1) {
                float* P = (wk == 3) ? P0 : P1;
#pragma unroll
                for (int mt = 0; mt < 2; mt++)
#pragma unroll
                    for (int j = 0; j < 6; j++) {
                        int r = 32 * wm + 16 * mt + (lane >> 2);
                        int cix = j * 8 + colb;
                        *(float2*)&P[r * P_STRIDE + cix]       = make_float2(acc[mt][j][0], acc[mt][j][1]);
                        *(float2*)&P[(r + 8) * P_STRIDE + cix] = make_float2(acc[mt][j][2], acc[mt][j][3]);
                    }
            }
        }
        __syncthreads();
        if (wk == 2 || wk == 0) {
            const float* P = (wk == 2) ? P0 : P1;
#pragma unroll
            for (int mt = 0; mt < 2; mt++)
#pragma unroll
                for (int j = 0; j < 6; j++) {
                    int r = 32 * wm + 16 * mt + (lane >> 2);
                    int cix = j * 8 + colb;
                    float2 p0 = *(const float2*)&P[r * P_STRIDE + cix];
                    float2 p1 = *(const float2*)&P[(r + 8) * P_STRIDE + cix];
                    acc[mt][j][0] += p0.x; acc[mt][j][1] += p0.y;
                    acc[mt][j][2] += p1.x; acc[mt][j][3] += p1.y;
                }
        }
        __syncthreads();
        if (wk == 2) {
#pragma unroll
            for (int mt = 0; mt < 2; mt++)
#pragma unroll
                for (int j = 0; j < 6; j++) {
                    int r = 32 * wm + 16 * mt + (lane >> 2);
                    int cix = j * 8 + colb;
                    *(float2*)&P0[r * P_STRIDE + cix]       = make_float2(acc[mt][j][0], acc[mt][j][1]);
                    *(float2*)&P0[(r + 8) * P_STRIDE + cix] = make_float2(acc[mt][j][2], acc[mt][j][3]);
                }
        }
        __syncthreads();
        if (wk == 0) {
            // final: += P0, + bias, store into P1 (= Ss)
#pragma unroll
            for (int mt = 0; mt < 2; mt++)
#pragma unroll
                for (int j = 0; j < 6; j++) {
                    int r = 32 * wm + 16 * mt + (lane >> 2);
                    int cix = j * 8 + colb;
                    float b0 = bhh[cix], b1 = bhh[cix + 1];
                    float2 p0 = *(const float2*)&P0[r * P_STRIDE + cix];
                    float2 p1 = *(const float2*)&P0[(r + 8) * P_STRIDE + cix];
                    *(float2*)&P1[r * P_STRIDE + cix] =
                        make_float2(acc[mt][j][0] + p0.x + b0, acc[mt][j][1] + p0.y + b1);
                    *(float2*)&P1[(r + 8) * P_STRIDE + cix] =
                        make_float2(acc[mt][j][2] + p1.x + b0, acc[mt][j][3] + p1.y + b1);
                }
        }
        __syncthreads();

        // ---- epilogue: gates + h update (1024 items, 4 per thread) ----
        const float* h_old = g_h32[t & 1];
        float*       h_new = g_h32[(t + 1) & 1];
        float*       hr_new = g_hr[(t + 1) & 1];
#pragma unroll
        for (int p = 0; p < 4; p++) {
            int item = tid + 256 * p;
            int b = item >> 4, u = item & 15;
            int hu = c * UPC + u;
            float sr = P1[b * P_STRIDE + u];
            float sz = P1[b * P_STRIDE + 16 + u];
            float sn = P1[b * P_STRIDE + 32 + u];
            const float* gi = g_gi + (size_t)(t * BATCH + b) * G3 + hu;
            float gr = gi[0], gz = gi[RNNSZ], gn = gi[2 * RNNSZ];
            float r = 1.f / (1.f + __expf(-(sr + gr)));
            float z = 1.f / (1.f + __expf(-(sz + gz)));
            float n = tanhf(gn + r * sn);
            float hprev = h_old[b * RNNSZ + hu];
            float hy = z * n + (1.f - z) * hprev;
            h_new[b * RNNSZ + hu] = hy;
            // permuted tf32 copy for next step's A-fragments
            int kk = u & 7, q = kk & 3, hi = kk >> 2, ksl = u >> 3;
            hr_new[b * RNNSZ + c * 16 + 4 * q + 2 * ksl + hi] = f2tf_f(hy);
        }
        __syncthreads();

        // ---- grid barrier ----
        if (tid == 0) {
            __threadfence();
            g_flags[c] = t + 1;
        }
        if (w == 0) {
            int target = t + 1;
            while (g_flags[lane] < target || g_flags[lane + 32] < target) {}
            __threadfence();
        }
        __syncthreads();
    }
}

// ------------------------- phase 3: FC head -------------------------
__global__ void fc_kernel(const float* __restrict__ fc_w,
                          const float* __restrict__ fc_b,
                          float* __restrict__ out) {
    int tid = threadIdx.x;          // 256 threads = 64 batches x 4 outputs
    int b = tid >> 2, o = tid & 3;
    const float* h = g_h32[0] + b * RNNSZ;   // after 512 steps, state is in buffer 0
    const float* wrow = fc_w + o * RNNSZ;
    float s = fc_b[o];
    for (int k = 0; k < RNNSZ; k += 4) {
        float4 hv = *(const float4*)(h + k);
        float4 wv = *(const float4*)(wrow + k);
        s += hv.x * wv.x + hv.y * wv.y + hv.z * wv.z + hv.w * wv.w;
    }
    out[b * 4 + o] = s;
}

// ------------------------- launch -------------------------
extern "C" void kernel_launch(void* const* d_in, const int* in_sizes, int n_in,
                              void* d_out, int out_size) {
    const int*   x    = (const int*)  d_in[0];
    const float* emb  = (const float*)d_in[1];
    const float* w_ih = (const float*)d_in[2];
    const float* w_hh = (const float*)d_in[3];
    const float* b_ih = (const float*)d_in[4];
    const float* b_hh = (const float*)d_in[5];
    const float* fc_w = (const float*)d_in[6];
    const float* fc_b = (const float*)d_in[7];
    float* out = (float*)d_out;

    static bool attr_done = false;
    if (!attr_done) {
        cudaFuncSetAttribute(rec_kernel, cudaFuncAttributeMaxDynamicSharedMemorySize, REC_SMEM);
        attr_done = true;
    }

    init_kernel<<<(BATCH * RNNSZ + 255) / 256, 256>>>();
    gi_kernel<<<dim3(G3 / 128, (T_STEPS * BATCH) / 128), 256>>>(x, emb, w_ih, b_ih);
    rec_kernel<<<NCTA, 256, REC_SMEM>>>(w_hh, b_hh);
    fc_kernel<<<1, 256>>>(fc_w, fc_b, out);
}

// round 16
// speedup vs baseline: 1.0508x; 1.0508x over previous
#include <cuda_runtime.h>
#include <cuda_bf16.h>
#include <cstdint>
#include <cstddef>

#define T_STEPS 512
#define BATCH   64
#define EMBD    512
#define RNNSZ   1024
#define G3      3072
#define NCTA    64
#define UPC     16          // hidden units per recurrence CTA
#define NCOL    48          // 3 gates * 16 units

// ------------------------- device scratch (no allocation) -------------------------
__device__ float g_gi[(size_t)T_STEPS * BATCH * G3];   // gi_all = emb[x] @ w_ih^T + b_ih
__device__ float g_h32[2][BATCH * RNNSZ];              // fp32 hidden state (ping-pong)
__device__ float g_hr [2][BATCH * RNNSZ];              // tf32-rounded hidden, k-permuted layout
__device__ volatile int g_flags[NCTA];                 // grid barrier flags
__device__ int g_dummy_sink;

// ------------------------- helpers -------------------------
__device__ __forceinline__ float f2tf_f(float f) {
    unsigned u;
    asm("cvt.rna.tf32.f32 %0, %1;" : "=r"(u) : "f"(f));
    return __uint_as_float(u);
}

__device__ __forceinline__ void mma8(float c[4],
                                     unsigned a0, unsigned a1, unsigned a2, unsigned a3,
                                     unsigned b0, unsigned b1) {
    asm volatile(
        "mma.sync.aligned.m16n8k8.row.col.f32.tf32.tf32.f32 "
        "{%0,%1,%2,%3},{%4,%5,%6,%7},{%8,%9},{%0,%1,%2,%3};"
        : "+f"(c[0]), "+f"(c[1]), "+f"(c[2]), "+f"(c[3])
        : "r"(a0), "r"(a1), "r"(a2), "r"(a3), "r"(b0), "r"(b1));
}

// ------------------------- dummy (shifts ncu capture slot onto rec_kernel) --------
__global__ void dummy_kernel() {
    if (threadIdx.x == 0) g_dummy_sink = 1;
}

// ------------------------- init -------------------------
__global__ void init_kernel() {
    int i = blockIdx.x * blockDim.x + threadIdx.x;
    if (i < BATCH * RNNSZ) { g_h32[0][i] = 0.f; g_hr[0][i] = 0.f; }
    if (blockIdx.x == 0 && threadIdx.x < NCTA) g_flags[threadIdx.x] = 0;
}

// ------------------------- phase 1: gi GEMM (gather fused) -------------------------
__global__ __launch_bounds__(256) void gi_kernel(const int* __restrict__ x,
                                                 const float* __restrict__ emb,
                                                 const float* __restrict__ w_ih,
                                                 const float* __restrict__ b_ih) {
    __shared__ float As[128][36];
    __shared__ float Bs[128][36];
    __shared__ int   toks[128];

    const int tid = threadIdx.x;
    const int m0 = blockIdx.y * 128;
    const int n0 = blockIdx.x * 128;
    if (tid < 128) toks[tid] = x[m0 + tid];
    __syncthreads();

    const int w = tid >> 5, lane = tid & 31;
    const int wm = (w & 3) * 32;
    const int wn = (w >> 2) * 64;

    float acc[2][8][4];
#pragma unroll
    for (int a = 0; a < 2; a++)
#pragma unroll
        for (int b = 0; b < 8; b++)
#pragma unroll
            for (int q = 0; q < 4; q++) acc[a][b][q] = 0.f;

    const int lrow = tid >> 1;
    const int lcb  = (tid & 1) * 16;
    const float* aptr = emb  + (size_t)toks[lrow] * EMBD + lcb;
    const float* bptr = w_ih + (size_t)(n0 + lrow) * EMBD + lcb;

    for (int kc = 0; kc < EMBD; kc += 32) {
#pragma unroll
        for (int q = 0; q < 4; q++) {
            float4 va = *(const float4*)(aptr + kc + q * 4);
            *(float4*)&As[lrow][lcb + q * 4] =
                make_float4(f2tf_f(va.x), f2tf_f(va.y), f2tf_f(va.z), f2tf_f(va.w));
            float4 vb = *(const float4*)(bptr + kc + q * 4);
            *(float4*)&Bs[lrow][lcb + q * 4] =
                make_float4(f2tf_f(vb.x), f2tf_f(vb.y), f2tf_f(vb.z), f2tf_f(vb.w));
        }
        __syncthreads();
#pragma unroll
        for (int ks = 0; ks < 4; ks++) {
            const int cc = ks * 8 + (lane & 3);
            unsigned a[2][4];
#pragma unroll
            for (int mt = 0; mt < 2; mt++) {
                int r = wm + mt * 16 + (lane >> 2);
                a[mt][0] = __float_as_uint(As[r][cc]);
                a[mt][1] = __float_as_uint(As[r + 8][cc]);
                a[mt][2] = __float_as_uint(As[r][cc + 4]);
                a[mt][3] = __float_as_uint(As[r + 8][cc + 4]);
            }
#pragma unroll
            for (int nt = 0; nt < 8; nt++) {
                int cl = wn + nt * 8 + (lane >> 2);
                unsigned b0 = __float_as_uint(Bs[cl][cc]);
                unsigned b1 = __float_as_uint(Bs[cl][cc + 4]);
                mma8(acc[0][nt], a[0][0], a[0][1], a[0][2], a[0][3], b0, b1);
                mma8(acc[1][nt], a[1][0], a[1][1], a[1][2], a[1][3], b0, b1);
            }
        }
        __syncthreads();
    }

#pragma unroll
    for (int mt = 0; mt < 2; mt++)
#pragma unroll
        for (int nt = 0; nt < 8; nt++) {
            int row = m0 + wm + mt * 16 + (lane >> 2);
            int col = n0 + wn + nt * 8 + (lane & 3) * 2;
            float2 bias = *(const float2*)(b_ih + col);
            float2 v0 = make_float2(acc[mt][nt][0] + bias.x, acc[mt][nt][1] + bias.y);
            float2 v1 = make_float2(acc[mt][nt][2] + bias.x, acc[mt][nt][3] + bias.y);
            *(float2*)&g_gi[(size_t)row * G3 + col]       = v0;
            *(float2*)&g_gi[(size_t)(row + 8) * G3 + col] = v1;
        }
}

// ------------------------- phase 2: persistent recurrence -------------------------
// 64 CTAs x 256 thr. CTA c owns hidden units [16c, 16c+16) -> 48 gh columns.
// Weights tf32-packed in smem (mma B-fragment order). Warps = 2(M-half) x 4(K-quarter).
// h stored permuted so A-fragments for 2 k-steps come from one LDG.128.
#define SMW_FLOATS (NCOL * RNNSZ)            // 49152
#define P_STRIDE   50
#define P_FLOATS   (BATCH * P_STRIDE)        // 3200
#define REC_SMEM   ((SMW_FLOATS + 2 * P_FLOATS + 64) * 4)

__global__ __launch_bounds__(256, 1) void rec_kernel(const float* __restrict__ w_hh,
                                                     const float* __restrict__ b_hh) {
    extern __shared__ float sm[];
    float* smw = sm;
    float* P0  = sm + SMW_FLOATS;
    float* P1  = P0 + P_FLOATS;               // also the final gate-sum buffer
    float* bhh = P1 + P_FLOATS;

    const int c   = blockIdx.x;
    const int tid = threadIdx.x;

    // ---- one-time: pack weights (tf32, B-fragment order) ----
    for (int idx = tid; idx < NCOL * RNNSZ; idx += 256) {
        int i = idx >> 10;                    // col-set 0..47
        int k = idx & (RNNSZ - 1);
        int gate = i >> 4, u = i & 15;
        float v = f2tf_f(w_hh[(size_t)(gate * RNNSZ + c * UPC + u) * RNNSZ + k]);
        int j = i >> 3, n_in = i & 7, ksg = k >> 3, kk = k & 7;
        int ln = n_in * 4 + (kk & 3), slot = kk >> 2;
        smw[((j * 128 + ksg) * 32 + ln) * 2 + slot] = v;
    }
    if (tid < NCOL) {
        int gate = tid >> 4, u = tid & 15;
        bhh[tid] = b_hh[gate * RNNSZ + c * UPC + u];
    }
    __syncthreads();

    const int w = tid >> 5, lane = tid & 31;
    const int wm = w & 1;                     // M half (rows 32*wm .. +32)
    const int wk = w >> 1;                    // K quarter

    // fixed per-thread row pointers (col offset added per k-group)
    const int rb = 32 * wm + (lane >> 2);
    const int lc4 = 4 * (lane & 3);

    for (int t = 0; t < T_STEPS; t++) {
        // ---- prefetch gi for this CTA's epilogue items (hides DRAM latency) ----
        float gpre[4][3];
#pragma unroll
        for (int p = 0; p < 4; p++) {
            int item = tid + 256 * p;
            int b = item >> 4, u = item & 15;
            const float* gi = g_gi + (size_t)(t * BATCH + b) * G3 + c * UPC + u;
            gpre[p][0] = __ldg(gi);
            gpre[p][1] = __ldg(gi + RNNSZ);
            gpre[p][2] = __ldg(gi + 2 * RNNSZ);
        }

        const float* hr = g_hr[t & 1];
        const float* p0r = hr + (size_t)rb * RNNSZ + lc4;
        const float* p1r = p0r + (size_t)8  * RNNSZ;
        const float* p2r = p0r + (size_t)16 * RNNSZ;
        const float* p3r = p0r + (size_t)24 * RNNSZ;

        float acc[2][6][4];
#pragma unroll
        for (int mt = 0; mt < 2; mt++)
#pragma unroll
            for (int j = 0; j < 6; j++)
#pragma unroll
                for (int q = 0; q < 4; q++) acc[mt][j][q] = 0.f;

        // ---- gh mma over this warp's K quarter, software-pipelined h loads ----
        const int gbase = wk * 16;
        float4 cur0 = *(const float4*)(p0r + gbase * 16);
        float4 cur1 = *(const float4*)(p1r + gbase * 16);
        float4 cur2 = *(const float4*)(p2r + gbase * 16);
        float4 cur3 = *(const float4*)(p3r + gbase * 16);
#pragma unroll 4
        for (int g16 = 0; g16 < 16; g16++) {
            float4 nxt0, nxt1, nxt2, nxt3;
            if (g16 < 15) {
                const int off = (gbase + g16 + 1) * 16;
                nxt0 = *(const float4*)(p0r + off);
                nxt1 = *(const float4*)(p1r + off);
                nxt2 = *(const float4*)(p2r + off);
                nxt3 = *(const float4*)(p3r + off);
            }
            unsigned av[2][8];
            av[0][0] = __float_as_uint(cur0.x); av[0][1] = __float_as_uint(cur1.x);
            av[0][2] = __float_as_uint(cur0.y); av[0][3] = __float_as_uint(cur1.y);
            av[0][4] = __float_as_uint(cur0.z); av[0][5] = __float_as_uint(cur1.z);
            av[0][6] = __float_as_uint(cur0.w); av[0][7] = __float_as_uint(cur1.w);
            av[1][0] = __float_as_uint(cur2.x); av[1][1] = __float_as_uint(cur3.x);
            av[1][2] = __float_as_uint(cur2.y); av[1][3] = __float_as_uint(cur3.y);
            av[1][4] = __float_as_uint(cur2.z); av[1][5] = __float_as_uint(cur3.z);
            av[1][6] = __float_as_uint(cur2.w); av[1][7] = __float_as_uint(cur3.w);

            const int gg = gbase + g16;
#pragma unroll
            for (int ksl = 0; ksl < 2; ksl++) {
                const int ksg = gg * 2 + ksl;
#pragma unroll
                for (int j = 0; j < 6; j++) {
                    const float2 bb = *(const float2*)&smw[((j * 128 + ksg) * 32 + lane) * 2];
                    unsigned b0 = __float_as_uint(bb.x), b1 = __float_as_uint(bb.y);
                    mma8(acc[0][j], av[0][ksl*4+0], av[0][ksl*4+1], av[0][ksl*4+2], av[0][ksl*4+3], b0, b1);
                    mma8(acc[1][j], av[1][ksl*4+0], av[1][ksl*4+1], av[1][ksl*4+2], av[1][ksl*4+3], b0, b1);
                }
            }
            cur0 = nxt0; cur1 = nxt1; cur2 = nxt2; cur3 = nxt3;
        }

        // ---- reduce 4 K-quarters: wk3->P0, wk1->P1; wk2+=P0, wk0+=P1; wk2->P0; wk0+=P0 ----
        const int colb = 2 * (lane & 3);
        if (wk == 3 || wk == 1) {
            float* P = (wk == 3) ? P0 : P1;
#pragma unroll
            for (int mt = 0; mt < 2; mt++)
#pragma unroll
                for (int j = 0; j < 6; j++) {
                    int r = 32 * wm + 16 * mt + (lane >> 2);
                    int cix = j * 8 + colb;
                    *(float2*)&P[r * P_STRIDE + cix]       = make_float2(acc[mt][j][0], acc[mt][j][1]);
                    *(float2*)&P[(r + 8) * P_STRIDE + cix] = make_float2(acc[mt][j][2], acc[mt][j][3]);
                }
        }
        __syncthreads();
        if (wk == 2 || wk == 0) {
            const float* P = (wk == 2) ? P0 : P1;
#pragma unroll
            for (int mt = 0; mt < 2; mt++)
#pragma unroll
                for (int j = 0; j < 6; j++) {
                    int r = 32 * wm + 16 * mt + (lane >> 2);
                    int cix = j * 8 + colb;
                    float2 q0 = *(const float2*)&P[r * P_STRIDE + cix];
                    float2 q1 = *(const float2*)&P[(r + 8) * P_STRIDE + cix];
                    acc[mt][j][0] += q0.x; acc[mt][j][1] += q0.y;
                    acc[mt][j][2] += q1.x; acc[mt][j][3] += q1.y;
                }
        }
        __syncthreads();
        if (wk == 2) {
#pragma unroll
            for (int mt = 0; mt < 2; mt++)
#pragma unroll
                for (int j = 0; j < 6; j++) {
                    int r = 32 * wm + 16 * mt + (lane >> 2);
                    int cix = j * 8 + colb;
                    *(float2*)&P0[r * P_STRIDE + cix]       = make_float2(acc[mt][j][0], acc[mt][j][1]);
                    *(float2*)&P0[(r + 8) * P_STRIDE + cix] = make_float2(acc[mt][j][2], acc[mt][j][3]);
                }
        }
        __syncthreads();
        if (wk == 0) {
#pragma unroll
            for (int mt = 0; mt < 2; mt++)
#pragma unroll
                for (int j = 0; j < 6; j++) {
                    int r = 32 * wm + 16 * mt + (lane >> 2);
                    int cix = j * 8 + colb;
                    float b0 = bhh[cix], b1 = bhh[cix + 1];
                    float2 q0 = *(const float2*)&P0[r * P_STRIDE + cix];
                    float2 q1 = *(const float2*)&P0[(r + 8) * P_STRIDE + cix];
                    *(float2*)&P1[r * P_STRIDE + cix] =
                        make_float2(acc[mt][j][0] + q0.x + b0, acc[mt][j][1] + q0.y + b1);
                    *(float2*)&P1[(r + 8) * P_STRIDE + cix] =
                        make_float2(acc[mt][j][2] + q1.x + b0, acc[mt][j][3] + q1.y + b1);
                }
        }
        __syncthreads();

        // ---- epilogue: gates + h update (1024 items, 4 per thread) ----
        const float* h_old = g_h32[t & 1];
        float*       h_new = g_h32[(t + 1) & 1];
        float*       hr_new = g_hr[(t + 1) & 1];
#pragma unroll
        for (int p = 0; p < 4; p++) {
            int item = tid + 256 * p;
            int b = item >> 4, u = item & 15;
            int hu = c * UPC + u;
            float sr = P1[b * P_STRIDE + u];
            float sz = P1[b * P_STRIDE + 16 + u];
            float sn = P1[b * P_STRIDE + 32 + u];
            float r = 1.f / (1.f + __expf(-(sr + gpre[p][0])));
            float z = 1.f / (1.f + __expf(-(sz + gpre[p][1])));
            float n = tanhf(gpre[p][2] + r * sn);
            float hprev = h_old[b * RNNSZ + hu];
            float hy = z * n + (1.f - z) * hprev;
            h_new[b * RNNSZ + hu] = hy;
            int kk = u & 7, q = kk & 3, hi = kk >> 2, ksl = u >> 3;
            hr_new[b * RNNSZ + c * 16 + 4 * q + 2 * ksl + hi] = f2tf_f(hy);
        }
        __syncthreads();

        // ---- grid barrier ----
        if (tid == 0) {
            __threadfence();
            g_flags[c] = t + 1;
        }
        if (w == 0) {
            int target = t + 1;
            while (g_flags[lane] < target || g_flags[lane + 32] < target) {}
            __threadfence();
        }
        __syncthreads();
    }
}

// ------------------------- phase 3: FC head (64 CTAs, warp per output) -----------
__global__ void fc_kernel(const float* __restrict__ fc_w,
                          const float* __restrict__ fc_b,
                          float* __restrict__ out) {
    int b = blockIdx.x;                       // batch
    int w = threadIdx.x >> 5, lane = threadIdx.x & 31;   // w = output index 0..3
    const float* h    = g_h32[0] + b * RNNSZ; // after 512 steps, state in buffer 0
    const float* wrow = fc_w + w * RNNSZ;
    float s = 0.f;
#pragma unroll
    for (int k = lane * 4; k < RNNSZ; k += 128) {
        float4 hv = *(const float4*)(h + k);
        float4 wv = *(const float4*)(wrow + k);
        s += hv.x * wv.x + hv.y * wv.y + hv.z * wv.z + hv.w * wv.w;
    }
#pragma unroll
    for (int off = 16; off; off >>= 1) s += __shfl_xor_sync(0xffffffffu, s, off);
    if (lane == 0) out[b * 4 + w] = s + fc_b[w];
}

// ------------------------- launch -------------------------
extern "C" void kernel_launch(void* const* d_in, const int* in_sizes, int n_in,
                              void* d_out, int out_size) {
    const int*   x    = (const int*)  d_in[0];
    const float* emb  = (const float*)d_in[1];
    const float* w_ih = (const float*)d_in[2];
    const float* w_hh = (const float*)d_in[3];
    const float* b_ih = (const float*)d_in[4];
    const float* b_hh = (const float*)d_in[5];
    const float* fc_w = (const float*)d_in[6];
    const float* fc_b = (const float*)d_in[7];
    float* out = (float*)d_out;

    static bool attr_done = false;
    if (!attr_done) {
        cudaFuncSetAttribute(rec_kernel, cudaFuncAttributeMaxDynamicSharedMemorySize, REC_SMEM);
        attr_done = true;
    }

    dummy_kernel<<<1, 32>>>();   // shifts ncu capture slot (#6) onto rec_kernel
    init_kernel<<<(BATCH * RNNSZ + 255) / 256, 256>>>();
    gi_kernel<<<dim3(G3 / 128, (T_STEPS * BATCH) / 128), 256>>>(x, emb, w_ih, b_ih);
    rec_kernel<<<NCTA, 256, REC_SMEM>>>(w_hh, b_hh);
    fc_kernel<<<BATCH, 128>>>(fc_w, fc_b, out);
}

// round 17
// speedup vs baseline: 1.4412x; 1.3715x over previous
#include <cuda_runtime.h>
#include <cuda_bf16.h>
#include <cstdint>
#include <cstddef>

#define T_STEPS 512
#define BATCH   64
#define EMBD    512
#define RNNSZ   1024
#define G3      3072
#define NCTA    128         // (batch-half) x (64 column groups)
#define UPC     16          // hidden units per column group
#define NCOL    48          // 3 gates * 16 units

// ------------------------- device scratch (no allocation) -------------------------
__device__ float g_gi[(size_t)T_STEPS * BATCH * G3];   // gi_all = emb[x] @ w_ih^T + b_ih
__device__ float g_h32[2][BATCH * RNNSZ];              // fp32 hidden state (ping-pong)
__device__ float g_hr [2][BATCH * RNNSZ];              // tf32-rounded hidden, k-permuted layout
__device__ volatile int g_flags[NCTA];                 // grid barrier flags
__device__ int g_dummy_sink;

// ------------------------- helpers -------------------------
__device__ __forceinline__ float f2tf_f(float f) {
    unsigned u;
    asm("cvt.rna.tf32.f32 %0, %1;" : "=r"(u) : "f"(f));
    return __uint_as_float(u);
}

__device__ __forceinline__ void mma8(float c[4],
                                     unsigned a0, unsigned a1, unsigned a2, unsigned a3,
                                     unsigned b0, unsigned b1) {
    asm volatile(
        "mma.sync.aligned.m16n8k8.row.col.f32.tf32.tf32.f32 "
        "{%0,%1,%2,%3},{%4,%5,%6,%7},{%8,%9},{%0,%1,%2,%3};"
        : "+f"(c[0]), "+f"(c[1]), "+f"(c[2]), "+f"(c[3])
        : "r"(a0), "r"(a1), "r"(a2), "r"(a3), "r"(b0), "r"(b1));
}

// ------------------------- dummy (shifts ncu capture slot onto rec_kernel) --------
__global__ void dummy_kernel() {
    if (threadIdx.x == 0) g_dummy_sink = 1;
}

// ------------------------- init -------------------------
__global__ void init_kernel() {
    int i = blockIdx.x * blockDim.x + threadIdx.x;
    if (i < BATCH * RNNSZ) { g_h32[0][i] = 0.f; g_hr[0][i] = 0.f; }
    if (blockIdx.x == 0 && threadIdx.x < NCTA) g_flags[threadIdx.x] = 0;
}

// ------------------------- phase 1: gi GEMM (gather fused) -------------------------
__global__ __launch_bounds__(256) void gi_kernel(const int* __restrict__ x,
                                                 const float* __restrict__ emb,
                                                 const float* __restrict__ w_ih,
                                                 const float* __restrict__ b_ih) {
    __shared__ float As[128][36];
    __shared__ float Bs[128][36];
    __shared__ int   toks[128];

    const int tid = threadIdx.x;
    const int m0 = blockIdx.y * 128;
    const int n0 = blockIdx.x * 128;
    if (tid < 128) toks[tid] = x[m0 + tid];
    __syncthreads();

    const int w = tid >> 5, lane = tid & 31;
    const int wm = (w & 3) * 32;
    const int wn = (w >> 2) * 64;

    float acc[2][8][4];
#pragma unroll
    for (int a = 0; a < 2; a++)
#pragma unroll
        for (int b = 0; b < 8; b++)
#pragma unroll
            for (int q = 0; q < 4; q++) acc[a][b][q] = 0.f;

    const int lrow = tid >> 1;
    const int lcb  = (tid & 1) * 16;
    const float* aptr = emb  + (size_t)toks[lrow] * EMBD + lcb;
    const float* bptr = w_ih + (size_t)(n0 + lrow) * EMBD + lcb;

    for (int kc = 0; kc < EMBD; kc += 32) {
#pragma unroll
        for (int q = 0; q < 4; q++) {
            float4 va = *(const float4*)(aptr + kc + q * 4);
            *(float4*)&As[lrow][lcb + q * 4] =
                make_float4(f2tf_f(va.x), f2tf_f(va.y), f2tf_f(va.z), f2tf_f(va.w));
            float4 vb = *(const float4*)(bptr + kc + q * 4);
            *(float4*)&Bs[lrow][lcb + q * 4] =
                make_float4(f2tf_f(vb.x), f2tf_f(vb.y), f2tf_f(vb.z), f2tf_f(vb.w));
        }
        __syncthreads();
#pragma unroll
        for (int ks = 0; ks < 4; ks++) {
            const int cc = ks * 8 + (lane & 3);
            unsigned a[2][4];
#pragma unroll
            for (int mt = 0; mt < 2; mt++) {
                int r = wm + mt * 16 + (lane >> 2);
                a[mt][0] = __float_as_uint(As[r][cc]);
                a[mt][1] = __float_as_uint(As[r + 8][cc]);
                a[mt][2] = __float_as_uint(As[r][cc + 4]);
                a[mt][3] = __float_as_uint(As[r + 8][cc + 4]);
            }
#pragma unroll
            for (int nt = 0; nt < 8; nt++) {
                int cl = wn + nt * 8 + (lane >> 2);
                unsigned b0 = __float_as_uint(Bs[cl][cc]);
                unsigned b1 = __float_as_uint(Bs[cl][cc + 4]);
                mma8(acc[0][nt], a[0][0], a[0][1], a[0][2], a[0][3], b0, b1);
                mma8(acc[1][nt], a[1][0], a[1][1], a[1][2], a[1][3], b0, b1);
            }
        }
        __syncthreads();
    }

#pragma unroll
    for (int mt = 0; mt < 2; mt++)
#pragma unroll
        for (int nt = 0; nt < 8; nt++) {
            int row = m0 + wm + mt * 16 + (lane >> 2);
            int col = n0 + wn + nt * 8 + (lane & 3) * 2;
            float2 bias = *(const float2*)(b_ih + col);
            float2 v0 = make_float2(acc[mt][nt][0] + bias.x, acc[mt][nt][1] + bias.y);
            float2 v1 = make_float2(acc[mt][nt][2] + bias.x, acc[mt][nt][3] + bias.y);
            *(float2*)&g_gi[(size_t)row * G3 + col]       = v0;
            *(float2*)&g_gi[(size_t)(row + 8) * G3 + col] = v1;
        }
}

// ------------------------- phase 2: persistent recurrence -------------------------
// 128 CTAs x 512 thr. CTA (bh, c): batch rows [32*bh, 32*bh+32), hidden units
// [16c, 16c+16) -> 48 gh columns. Weights tf32-packed in smem (B-fragment order).
// Warps = 2(M: 16 rows) x 8(K: 128 each). 8-way K reduction via 3-stage smem tree.
#define SMW_FLOATS (NCOL * RNNSZ)            // 49152
#define P_STRIDE   50
#define P_ROWS     32
#define P_FLOATS   (P_ROWS * P_STRIDE)       // 1600
#define REC_SMEM   ((SMW_FLOATS + 4 * P_FLOATS + 64) * 4)

__global__ __launch_bounds__(512, 1) void rec_kernel(const float* __restrict__ w_hh,
                                                     const float* __restrict__ b_hh) {
    extern __shared__ float sm[];
    float* smw = sm;
    float* Pb[4];
    Pb[0] = sm + SMW_FLOATS;
    Pb[1] = Pb[0] + P_FLOATS;
    Pb[2] = Pb[1] + P_FLOATS;
    Pb[3] = Pb[2] + P_FLOATS;
    float* bhh = Pb[3] + P_FLOATS;

    const int bh  = blockIdx.x >> 6;          // batch half
    const int c   = blockIdx.x & 63;          // column group
    const int tid = threadIdx.x;

    // ---- one-time: pack weights (tf32, B-fragment order; same formula as R15) ----
    for (int idx = tid; idx < NCOL * RNNSZ; idx += 512) {
        int i = idx >> 10;                    // col-set 0..47
        int k = idx & (RNNSZ - 1);
        int gate = i >> 4, u = i & 15;
        float v = f2tf_f(w_hh[(size_t)(gate * RNNSZ + c * UPC + u) * RNNSZ + k]);
        int j = i >> 3, n_in = i & 7, ksg = k >> 3, kk = k & 7;
        int ln = n_in * 4 + (kk & 3), slot = kk >> 2;
        smw[((j * 128 + ksg) * 32 + ln) * 2 + slot] = v;
    }
    if (tid < NCOL) {
        int gate = tid >> 4, u = tid & 15;
        bhh[tid] = b_hh[gate * RNNSZ + c * UPC + u];
    }
    __syncthreads();

    const int w = tid >> 5, lane = tid & 31;
    const int wm = w & 1;                     // M half: rows 32*bh + 16*wm .. +16
    const int wk = w >> 1;                    // K eighth (0..7)

    const int rb  = 32 * bh + 16 * wm + (lane >> 2);   // global batch row of frag row 0
    const int lc4 = 4 * (lane & 3);
    const int rloc = 16 * wm + (lane >> 2);            // local row in P buffers
    const int colb = 2 * (lane & 3);

    // epilogue item: one per thread
    const int lb = tid >> 4;                  // local batch 0..31
    const int eu = tid & 15;                  // unit within group
    const int eb = 32 * bh + lb;              // global batch
    const int ehu = c * UPC + eu;

    for (int t = 0; t < T_STEPS; t++) {
        // ---- prefetch gi for this thread's epilogue item ----
        const float* gi = g_gi + (size_t)(t * BATCH + eb) * G3 + ehu;
        float g0 = __ldg(gi), g1 = __ldg(gi + RNNSZ), g2 = __ldg(gi + 2 * RNNSZ);

        const float* hr = g_hr[t & 1];
        const float* p0r = hr + (size_t)rb * RNNSZ + lc4;
        const float* p1r = p0r + (size_t)8 * RNNSZ;

        float acc[6][4];
#pragma unroll
        for (int j = 0; j < 6; j++)
#pragma unroll
            for (int q = 0; q < 4; q++) acc[j][q] = 0.f;

        // ---- gh mma over this warp's K eighth (8 groups of 16 k), pipelined ----
        const int gbase = wk * 8;
        float4 cur0 = *(const float4*)(p0r + gbase * 16);
        float4 cur1 = *(const float4*)(p1r + gbase * 16);
#pragma unroll
        for (int g16 = 0; g16 < 8; g16++) {
            float4 nxt0, nxt1;
            if (g16 < 7) {
                const int off = (gbase + g16 + 1) * 16;
                nxt0 = *(const float4*)(p0r + off);
                nxt1 = *(const float4*)(p1r + off);
            }
            unsigned av[8];
            av[0] = __float_as_uint(cur0.x); av[1] = __float_as_uint(cur1.x);
            av[2] = __float_as_uint(cur0.y); av[3] = __float_as_uint(cur1.y);
            av[4] = __float_as_uint(cur0.z); av[5] = __float_as_uint(cur1.z);
            av[6] = __float_as_uint(cur0.w); av[7] = __float_as_uint(cur1.w);

            const int gg = gbase + g16;
#pragma unroll
            for (int ksl = 0; ksl < 2; ksl++) {
                const int ksg = gg * 2 + ksl;
#pragma unroll
                for (int j = 0; j < 6; j++) {
                    const float2 bb = *(const float2*)&smw[((j * 128 + ksg) * 32 + lane) * 2];
                    mma8(acc[j], av[ksl*4+0], av[ksl*4+1], av[ksl*4+2], av[ksl*4+3],
                         __float_as_uint(bb.x), __float_as_uint(bb.y));
                }
            }
            cur0 = nxt0; cur1 = nxt1;
        }

        // ---- 8-way K reduction: (4..7 -> P0..3) += (0..3); (2,3 -> P0,1) += (0,1);
        //      (1 -> P0) += 0; + bias -> P1 ----
        if (wk >= 4) {
            float* P = Pb[wk - 4];
#pragma unroll
            for (int j = 0; j < 6; j++) {
                int cix = j * 8 + colb;
                *(float2*)&P[rloc * P_STRIDE + cix]       = make_float2(acc[j][0], acc[j][1]);
                *(float2*)&P[(rloc + 8) * P_STRIDE + cix] = make_float2(acc[j][2], acc[j][3]);
            }
        }
        __syncthreads();
        if (wk < 4) {
            const float* P = Pb[wk];
#pragma unroll
            for (int j = 0; j < 6; j++) {
                int cix = j * 8 + colb;
                float2 q0 = *(const float2*)&P[rloc * P_STRIDE + cix];
                float2 q1 = *(const float2*)&P[(rloc + 8) * P_STRIDE + cix];
                acc[j][0] += q0.x; acc[j][1] += q0.y;
                acc[j][2] += q1.x; acc[j][3] += q1.y;
            }
        }
        __syncthreads();
        if (wk == 2 || wk == 3) {
            float* P = Pb[wk - 2];
#pragma unroll
            for (int j = 0; j < 6; j++) {
                int cix = j * 8 + colb;
                *(float2*)&P[rloc * P_STRIDE + cix]       = make_float2(acc[j][0], acc[j][1]);
                *(float2*)&P[(rloc + 8) * P_STRIDE + cix] = make_float2(acc[j][2], acc[j][3]);
            }
        }
        __syncthreads();
        if (wk == 0 || wk == 1) {
            const float* P = Pb[wk];
#pragma unroll
            for (int j = 0; j < 6; j++) {
                int cix = j * 8 + colb;
                float2 q0 = *(const float2*)&P[rloc * P_STRIDE + cix];
                float2 q1 = *(const float2*)&P[(rloc + 8) * P_STRIDE + cix];
                acc[j][0] += q0.x; acc[j][1] += q0.y;
                acc[j][2] += q1.x; acc[j][3] += q1.y;
            }
        }
        __syncthreads();
        if (wk == 1) {
#pragma unroll
            for (int j = 0; j < 6; j++) {
                int cix = j * 8 + colb;
                *(float2*)&Pb[0][rloc * P_STRIDE + cix]       = make_float2(acc[j][0], acc[j][1]);
                *(float2*)&Pb[0][(rloc + 8) * P_STRIDE + cix] = make_float2(acc[j][2], acc[j][3]);
            }
        }
        __syncthreads();
        if (wk == 0) {
#pragma unroll
            for (int j = 0; j < 6; j++) {
                int cix = j * 8 + colb;
                float b0 = bhh[cix], b1 = bhh[cix + 1];
                float2 q0 = *(const float2*)&Pb[0][rloc * P_STRIDE + cix];
                float2 q1 = *(const float2*)&Pb[0][(rloc + 8) * P_STRIDE + cix];
                *(float2*)&Pb[1][rloc * P_STRIDE + cix] =
                    make_float2(acc[j][0] + q0.x + b0, acc[j][1] + q0.y + b1);
                *(float2*)&Pb[1][(rloc + 8) * P_STRIDE + cix] =
                    make_float2(acc[j][2] + q1.x + b0, acc[j][3] + q1.y + b1);
            }
        }
        __syncthreads();

        // ---- epilogue: gates + h update (512 items, 1 per thread) ----
        {
            const float* S = Pb[1];
            float sr = S[lb * P_STRIDE + eu];
            float sz = S[lb * P_STRIDE + 16 + eu];
            float sn = S[lb * P_STRIDE + 32 + eu];
            float r = 1.f / (1.f + __expf(-(sr + g0)));
            float z = 1.f / (1.f + __expf(-(sz + g1)));
            float n = tanhf(g2 + r * sn);
            float hprev = g_h32[t & 1][eb * RNNSZ + ehu];
            float hy = z * n + (1.f - z) * hprev;
            g_h32[(t + 1) & 1][eb * RNNSZ + ehu] = hy;
            int kk = eu & 7, q = kk & 3, hi = kk >> 2, ksl = eu >> 3;
            g_hr[(t + 1) & 1][eb * RNNSZ + c * 16 + 4 * q + 2 * ksl + hi] = f2tf_f(hy);
        }
        __syncthreads();

        // ---- grid barrier (128 CTAs) ----
        if (tid == 0) {
            __threadfence();
            g_flags[blockIdx.x] = t + 1;
        }
        if (w == 0) {
            int target = t + 1;
            while (g_flags[lane] < target || g_flags[lane + 32] < target ||
                   g_flags[lane + 64] < target || g_flags[lane + 96] < target) {}
            __threadfence();
        }
        __syncthreads();
    }
}

// ------------------------- phase 3: FC head (64 CTAs, warp per output) -----------
__global__ void fc_kernel(const float* __restrict__ fc_w,
                          const float* __restrict__ fc_b,
                          float* __restrict__ out) {
    int b = blockIdx.x;
    int w = threadIdx.x >> 5, lane = threadIdx.x & 31;
    const float* h    = g_h32[0] + b * RNNSZ;   // 512 steps -> state in buffer 0
    const float* wrow = fc_w + w * RNNSZ;
    float s = 0.f;
#pragma unroll
    for (int k = lane * 4; k < RNNSZ; k += 128) {
        float4 hv = *(const float4*)(h + k);
        float4 wv = *(const float4*)(wrow + k);
        s += hv.x * wv.x + hv.y * wv.y + hv.z * wv.z + hv.w * wv.w;
    }
#pragma unroll
    for (int off = 16; off; off >>= 1) s += __shfl_xor_sync(0xffffffffu, s, off);
    if (lane == 0) out[b * 4 + w] = s + fc_b[w];
}

// ------------------------- launch -------------------------
extern "C" void kernel_launch(void* const* d_in, const int* in_sizes, int n_in,
                              void* d_out, int out_size) {
    const int*   x    = (const int*)  d_in[0];
    const float* emb  = (const float*)d_in[1];
    const float* w_ih = (const float*)d_in[2];
    const float* w_hh = (const float*)d_in[3];
    const float* b_ih = (const float*)d_in[4];
    const float* b_hh = (const float*)d_in[5];
    const float* fc_w = (const float*)d_in[6];
    const float* fc_b = (const float*)d_in[7];
    float* out = (float*)d_out;

    static bool attr_done = false;
    if (!attr_done) {
        cudaFuncSetAttribute(rec_kernel, cudaFuncAttributeMaxDynamicSharedMemorySize, REC_SMEM);
        attr_done = true;
    }

    dummy_kernel<<<1, 32>>>();   // keeps ncu capture slot (#6) on rec_kernel
    init_kernel<<<(BATCH * RNNSZ + 255) / 256, 256>>>();
    gi_kernel<<<dim3(G3 / 128, (T_STEPS * BATCH) / 128), 256>>>(x, emb, w_ih, b_ih);
    rec_kernel<<<NCTA, 512, REC_SMEM>>>(w_hh, b_hh);
    fc_kernel<<<BATCH, 128>>>(fc_w, fc_b, out);
}